// round 10
// baseline (speedup 1.0000x reference)
#include <cuda_runtime.h>
#include <cuda_bf16.h>
#include <math.h>
#include <stdint.h>

// Problem constants
#define Bc 16
#define Nc 5
#define Tc 10
#define Hc 512
#define Ec 250
#define Vc 30000
#define Fc 2048
#define H4 2048
#define H2 1024
#define NTB (Nc*Tc*Bc)   // 800
#define NBLK 128
#define SHS 1548         // smem h row stride (floats); /4=387 odd -> conflict-free stores

// packed fp32x2 FMA (SASS FFMA2)
#define FMA2(d, a, b) asm("fma.rn.f32x2 %0, %1, %2, %0;" : "+l"(d) : "l"(a), "l"(b))

__device__ __forceinline__ float f2lo(unsigned long long v) { return __uint_as_float((unsigned)v); }
__device__ __forceinline__ float f2hi(unsigned long long v) { return __uint_as_float((unsigned)(v >> 32)); }

// ---------------- device scratch ----------------
__device__ __align__(16) float g_tmp[Bc*H2];
__device__ __align__(16) float g_tmp2[Bc*H2];
__device__ __align__(16) float g_h0[Bc*Hc];          // [b][k]
__device__ __align__(16) float g_c0[Bc*Hc];          // [b][k]
__device__ __align__(16) float g_hst[4][2][Bc*Hc];   // state h, [b][k]
__device__ __align__(16) float g_cst[4][Bc*Hc];      // state c, [b][k]
__device__ __align__(16) float g_x0[NTB*Ec];
__device__ __align__(16) float g_xg0[2*NTB*H4];
__device__ __align__(16) float g_x1[Tc*Bc*H2];       // [t][b][1024]
__device__ __align__(16) float g_out1[NTB*H2];
__device__ __align__(16) float g_W0T[2*H4*Hc];
__device__ __align__(16) float g_W1T[2*H4*(Hc+H2)];
__device__ __align__(16) __nv_bfloat16 g_Ahi[NTB*H2];
__device__ __align__(16) __nv_bfloat16 g_Alo[NTB*H2];
__device__ __align__(16) __nv_bfloat16 g_Bhi[(size_t)Vc*H2];
__device__ __align__(16) __nv_bfloat16 g_Blo[(size_t)Vc*H2];

__device__ unsigned g_barcnt = 0;
__device__ unsigned g_barsense = 0;

// ---------------- shared bodies ----------------
struct TParam { const float* in; float* out; int R; int ostride; };
struct TParams6 { TParam p[6]; };

__device__ __forceinline__ void sgemm_body(
    const float* A, const float* W, const float* bias, float* C,
    int M, int N, int K, int relu, int bm, int bn, int tid,
    float* As, float* Bs)   // As: 1024 floats [c*64+r], Bs: 1024 floats [r*64+c]
{
    int tm = (tid >> 4) << 2;
    int tn = (tid & 15) << 2;
    float acc[4][4] = {};
    for (int k0 = 0; k0 < K; k0 += 16) {
        #pragma unroll
        for (int e = 0; e < 4; e++) {
            int idx = tid + e * 256;
            int r = idx >> 4, c = idx & 15;
            int gr = bm + r, gc = k0 + c;
            As[c * 64 + r] = (gr < M && gc < K) ? A[(size_t)gr * K + gc] : 0.f;
        }
        #pragma unroll
        for (int e = 0; e < 4; e++) {
            int idx = tid + e * 256;
            int r = idx >> 6, c = idx & 63;
            int gr = k0 + r, gc = bn + c;
            Bs[r * 64 + c] = (gr < K && gc < N) ? W[(size_t)gr * N + gc] : 0.f;
        }
        __syncthreads();
        #pragma unroll
        for (int kk = 0; kk < 16; kk++) {
            float4 a4 = *(const float4*)&As[kk * 64 + tm];
            float4 b4 = *(const float4*)&Bs[kk * 64 + tn];
            float a[4] = {a4.x, a4.y, a4.z, a4.w};
            float b[4] = {b4.x, b4.y, b4.z, b4.w};
            #pragma unroll
            for (int i = 0; i < 4; i++)
                #pragma unroll
                for (int j = 0; j < 4; j++)
                    acc[i][j] = fmaf(a[i], b[j], acc[i][j]);
        }
        __syncthreads();
    }
    #pragma unroll
    for (int i = 0; i < 4; i++) {
        int gm = bm + tm + i;
        if (gm >= M) continue;
        #pragma unroll
        for (int j = 0; j < 4; j++) {
            int gn = bn + tn + j;
            if (gn >= N) continue;
            float v = acc[i][j] + bias[gn];
            if (relu) v = fmaxf(v, 0.f);
            C[(size_t)gm * N + gn] = v;
        }
    }
}

// ================= pre1: transposes + MLP stage1 + gather + convB =================
#define P1_TRANS 12288           // 6 * 64 * 32
#define P1_MLP   (P1_TRANS + 32)
#define P1_GATH  (P1_MLP + 800)
#define P1_TOTAL (P1_GATH + 30016)   // 938*32 convB blocks

__global__ __launch_bounds__(256) void pre1(
    TParams6 tp,
    const float* __restrict__ img,
    const float* __restrict__ Wh1, const float* __restrict__ bh1,
    const float* __restrict__ Wc1, const float* __restrict__ bc1,
    const int* __restrict__ caps, const float* __restrict__ emb,
    const float* __restrict__ Wfc)
{
    __shared__ float sh[2048];
    int id = blockIdx.x, tid = threadIdx.x;
    int tx = tid & 31, ty = tid >> 5;

    if (id < P1_TRANS) {
        int which = id / 2048, rem = id % 2048;
        int bx = rem & 63, by = rem >> 6;
        TParam p = tp.p[which];
        int c0 = bx * 32, r0 = by * 32;
        if (r0 >= p.R) return;
        for (int j = ty; j < 32; j += 8) {
            int r = r0 + j, c = c0 + tx;
            sh[j * 33 + tx] = (r < p.R) ? p.in[(size_t)r * H4 + c] : 0.f;
        }
        __syncthreads();
        for (int j = ty; j < 32; j += 8) {
            int c = c0 + j, r = r0 + tx;
            if (r < p.R) p.out[(size_t)c * p.ostride + r] = sh[tx * 33 + j];
        }
    } else if (id < P1_MLP) {
        int sub = id - P1_TRANS;
        int z = sub >> 4, bx = sub & 15;
        sgemm_body(img, z ? Wc1 : Wh1, z ? bc1 : bh1, z ? g_tmp2 : g_tmp,
                   Bc, H2, Fc, 1, 0, bx * 64, tid, sh, sh + 1024);
    } else if (id < P1_GATH) {
        int rid = id - P1_MLP;
        int b = rid & 15;
        int nt = rid >> 4;
        int n = nt / Tc, t = nt % Tc;
        int tok = caps[b * (Nc * Tc) + n * Tc + t];
        const float* e = emb + (size_t)tok * Ec;
        float* o = g_x0 + (size_t)rid * Ec;
        for (int i = tid; i < Ec; i += 256) o[i] = e[i];
    } else {
        int sub = id - P1_GATH;
        int n0 = (sub % 938) * 32, k0 = (sub / 938) * 32;
        for (int j = ty; j < 32; j += 8) {
            int k = k0 + j, n = n0 + tx;
            sh[j * 33 + tx] = (n < Vc) ? Wfc[(size_t)k * Vc + n] : 0.f;
        }
        __syncthreads();
        for (int j = ty; j < 32; j += 8) {
            int n = n0 + j, k = k0 + tx;
            if (n < Vc) {
                float v = sh[tx * 33 + j];
                __nv_bfloat16 h = __float2bfloat16(v);
                g_Bhi[(size_t)n * H2 + k] = h;
                g_Blo[(size_t)n * H2 + k] = __float2bfloat16(v - __bfloat162float(h));
            }
        }
    }
}

// ================= pre2: MLP stage2 (dual via z) =================
__global__ __launch_bounds__(256) void pre2()
{
    __shared__ float sh[2048];
    int z = blockIdx.z;
    sgemm_body(z ? g_tmp2 : g_tmp, nullptr, nullptr, nullptr, 0,0,0,0,0,0,0, nullptr, nullptr); // never: placeholder removed below
}

// (pre2 implemented as a proper kernel with weight args)
__global__ __launch_bounds__(256) void pre2k(
    const float* __restrict__ Wh2, const float* __restrict__ bh2,
    const float* __restrict__ Wc2, const float* __restrict__ bc2)
{
    __shared__ float sh[2048];
    int z = blockIdx.z;
    sgemm_body(z ? g_tmp2 : g_tmp, z ? Wc2 : Wh2, z ? bc2 : bh2, z ? g_c0 : g_h0,
               Bc, Hc, H2, 1, 0, blockIdx.x * 64, threadIdx.x, sh, sh + 1024);
}

// ================= pre3: xg0 GEMM (z=0,1) + state broadcast (z=2) =================
__global__ __launch_bounds__(256) void pre3(
    const float* __restrict__ B0, const float* __restrict__ bias0,
    const float* __restrict__ B1, const float* __restrict__ bias1)
{
    __shared__ __align__(16) float As[2][16][128];
    __shared__ __align__(16) float Bs[2][16][256];

    if (blockIdx.z == 2) {
        int lin = blockIdx.y * 16 + blockIdx.x;
        if (lin < 32) {
            int i = lin * 256 + threadIdx.x;
            float h = g_h0[i], c = g_c0[i];
            #pragma unroll
            for (int s = 0; s < 4; s++) {
                g_hst[s][0][i] = h;
                g_cst[s][i]    = c;
            }
        }
        return;
    }

    const float* A = g_x0;
    const float* B = blockIdx.z ? B1 : B0;
    const float* bias = blockIdx.z ? bias1 : bias0;
    float* C = blockIdx.z ? (g_xg0 + (size_t)NTB * H4) : g_xg0;
    const int M = NTB, N = H4, K = Ec;

    int tid = threadIdx.x;
    int bm = blockIdx.y * 128, bn = blockIdx.x * 128;
    int tx = tid & 15, ty = tid >> 4;
    int ar = tid >> 2, ac = (tid & 3) * 4;
    int br = tid >> 5, bc = (tid & 31) * 4;
    bool fullM = (bm + 128 <= M);

    unsigned long long acc[4][8];
    #pragma unroll
    for (int i = 0; i < 4; i++)
        #pragma unroll
        for (int j = 0; j < 8; j++) acc[i][j] = 0ull;

    float a0[4], a1[4], b0[4], b1[4];
    int KT = (K + 15) / 16;

#define LOADTILE(KT_) do {                                                        \
    int k0 = (KT_) * 16;                                                          \
    int gr0 = bm + ar, gr1 = bm + ar + 64;                                        \
    _Pragma("unroll") for (int j = 0; j < 4; j++) {                               \
        int gk = k0 + ac + j;                                                     \
        bool ok = (gk < K);                                                       \
        a0[j] = (ok && gr0 < M) ? A[(size_t)gr0 * K + gk] : 0.f;                  \
        a1[j] = (ok && gr1 < M) ? A[(size_t)gr1 * K + gk] : 0.f;                  \
    }                                                                             \
    int gk0 = k0 + br, gk1 = k0 + br + 8;                                         \
    if (gk0 + 0 < K || true) {                                                    \
        _Pragma("unroll") for (int j = 0; j < 4; j++) {                           \
            int gc = bn + bc + j;                                                 \
            b0[j] = (gk0 < K) ? B[(size_t)gk0 * N + gc] : 0.f;                    \
            b1[j] = (gk1 < K) ? B[(size_t)gk1 * N + gc] : 0.f;                    \
        }                                                                         \
    }                                                                             \
} while (0)

#define STORETILE(BUF_) do {                                                      \
    _Pragma("unroll") for (int j = 0; j < 4; j++) {                               \
        As[BUF_][ac + j][ar]      = a0[j];                                        \
        As[BUF_][ac + j][ar + 64] = a1[j];                                        \
        Bs[BUF_][br][(bc + j) * 2]         = b0[j];                               \
        Bs[BUF_][br][(bc + j) * 2 + 1]     = b0[j];                               \
        Bs[BUF_][br + 8][(bc + j) * 2]     = b1[j];                               \
        Bs[BUF_][br + 8][(bc + j) * 2 + 1] = b1[j];                               \
    }                                                                             \
} while (0)

    LOADTILE(0);
    STORETILE(0);
    __syncthreads();

    for (int kt = 0; kt < KT; kt++) {
        int cur = kt & 1;
        if (kt + 1 < KT) LOADTILE(kt + 1);
        #pragma unroll
        for (int k = 0; k < 16; k++) {
            unsigned long long a2[4], b2[8];
            #pragma unroll
            for (int i = 0; i < 4; i++)
                a2[i] = *(const unsigned long long*)&As[cur][k][ty * 8 + 2 * i];
            #pragma unroll
            for (int j = 0; j < 8; j++)
                b2[j] = *(const unsigned long long*)&Bs[cur][k][(tx + 16 * j) * 2];
            #pragma unroll
            for (int i = 0; i < 4; i++)
                #pragma unroll
                for (int j = 0; j < 8; j++)
                    FMA2(acc[i][j], a2[i], b2[j]);
        }
        if (kt + 1 < KT) STORETILE(cur ^ 1);
        __syncthreads();
    }

    #pragma unroll
    for (int j = 0; j < 8; j++) {
        int col = bn + tx + 16 * j;
        float bb = bias[col];
        #pragma unroll
        for (int i = 0; i < 4; i++) {
            int r0 = bm + ty * 8 + 2 * i;
            float lo = f2lo(acc[i][j]) + bb;
            float hi = f2hi(acc[i][j]) + bb;
            if (r0 < M)     C[(size_t)r0 * N + col] = lo;
            if (r0 + 1 < M) C[(size_t)(r0 + 1) * N + col] = hi;
        }
    }
#undef LOADTILE
#undef STORETILE
}

// ================= persistent recurrent kernel =================
__device__ __forceinline__ void grid_bar(unsigned& sense)
{
    __syncthreads();
    sense ^= 1;
    if (threadIdx.x == 0) {
        __threadfence();
        unsigned old = atomicAdd(&g_barcnt, 1);
        if (old == NBLK - 1) {
            g_barcnt = 0;
            __threadfence();
            atomicExch(&g_barsense, sense);
        } else {
            while (*(volatile unsigned*)&g_barsense != sense) __nanosleep(32);
        }
        __threadfence();
    }
    __syncthreads();
}

template<int LAYER>
__device__ __forceinline__ void lstm_do_step(
    int tid, int dir, int bkid, int ksub, int bs, int rg,
    float* hs, float* red,
    int n, int tok, int par,
    const float* bias1, const float* xg0d, unsigned& sense)
{
    const int K = LAYER ? (Hc + H2) : Hc;
    int slot = LAYER ? (2 + dir) : dir;
    const float* hglob = &g_hst[slot][par][0];   // [b][Hc]
    float* hout = &g_hst[slot][par ^ 1][0];
    float* cst  = &g_cst[slot][0];               // [b][Hc]
    const float* WT = LAYER ? (g_W1T + (size_t)dir * H4 * (Hc + H2))
                            : (g_W0T + (size_t)dir * H4 * Hc);

    // stage A: stage h (and x1 for layer1) into b-major smem rows
    {
        const float* x1g = g_x1 + (size_t)tok * Bc * H2;   // [b][H2]
        int nf4 = K * 4;
        for (int idx = tid; idx < nf4; idx += 256) {
            int b = idx & 15, k = (idx >> 4) * 4;
            float4 v;
            if (!LAYER || k < Hc) v = *(const float4*)&hglob[(size_t)b * Hc + k];
            else                  v = *(const float4*)&x1g[(size_t)b * H2 + (k - Hc)];
            *(float4*)&hs[b * SHS + k] = v;
        }
    }
    __syncthreads();

    // stage B: k-pair packed dot products (no splats)
    int r0 = rg * 4;
    const ulonglong2 *p0, *p1, *p2, *p3;
    {
        int m0 = ((r0 + 0) >> 3) * Hc + bkid * 8 + ((r0 + 0) & 7);
        int m1 = ((r0 + 1) >> 3) * Hc + bkid * 8 + ((r0 + 1) & 7);
        int m2 = ((r0 + 2) >> 3) * Hc + bkid * 8 + ((r0 + 2) & 7);
        int m3 = ((r0 + 3) >> 3) * Hc + bkid * 8 + ((r0 + 3) & 7);
        p0 = (const ulonglong2*)(WT + (size_t)m0 * K);
        p1 = (const ulonglong2*)(WT + (size_t)m1 * K);
        p2 = (const ulonglong2*)(WT + (size_t)m2 * K);
        p3 = (const ulonglong2*)(WT + (size_t)m3 * K);
    }
    unsigned long long acc[4][4];
    #pragma unroll
    for (int i = 0; i < 4; i++)
        #pragma unroll
        for (int j = 0; j < 4; j++) acc[i][j] = 0ull;

    const int K32 = K / 32;
    int b0 = bs * 4;
    const float* h0p = hs + (b0 + 0) * SHS;
    const float* h1p = hs + (b0 + 1) * SHS;
    const float* h2p = hs + (b0 + 2) * SHS;
    const float* h3p = hs + (b0 + 3) * SHS;

    ulonglong2 c0 = p0[ksub], c1 = p1[ksub], c2 = p2[ksub], c3 = p3[ksub];
    #pragma unroll 2
    for (int i = 0; i < K32; i++) {
        int nf = ((i + 1 < K32) ? (i + 1) : i) * 8 + ksub;
        ulonglong2 n0 = p0[nf], n1 = p1[nf], n2 = p2[nf], n3 = p3[nf];
        int k0 = i * 32 + ksub * 4;
        ulonglong2 h0 = *(const ulonglong2*)(h0p + k0);
        ulonglong2 h1 = *(const ulonglong2*)(h1p + k0);
        ulonglong2 h2 = *(const ulonglong2*)(h2p + k0);
        ulonglong2 h3 = *(const ulonglong2*)(h3p + k0);
        FMA2(acc[0][0], c0.x, h0.x); FMA2(acc[0][0], c0.y, h0.y);
        FMA2(acc[0][1], c0.x, h1.x); FMA2(acc[0][1], c0.y, h1.y);
        FMA2(acc[0][2], c0.x, h2.x); FMA2(acc[0][2], c0.y, h2.y);
        FMA2(acc[0][3], c0.x, h3.x); FMA2(acc[0][3], c0.y, h3.y);
        FMA2(acc[1][0], c1.x, h0.x); FMA2(acc[1][0], c1.y, h0.y);
        FMA2(acc[1][1], c1.x, h1.x); FMA2(acc[1][1], c1.y, h1.y);
        FMA2(acc[1][2], c1.x, h2.x); FMA2(acc[1][2], c1.y, h2.y);
        FMA2(acc[1][3], c1.x, h3.x); FMA2(acc[1][3], c1.y, h3.y);
        FMA2(acc[2][0], c2.x, h0.x); FMA2(acc[2][0], c2.y, h0.y);
        FMA2(acc[2][1], c2.x, h1.x); FMA2(acc[2][1], c2.y, h1.y);
        FMA2(acc[2][2], c2.x, h2.x); FMA2(acc[2][2], c2.y, h2.y);
        FMA2(acc[2][3], c2.x, h3.x); FMA2(acc[2][3], c2.y, h3.y);
        FMA2(acc[3][0], c3.x, h0.x); FMA2(acc[3][0], c3.y, h0.y);
        FMA2(acc[3][1], c3.x, h1.x); FMA2(acc[3][1], c3.y, h1.y);
        FMA2(acc[3][2], c3.x, h2.x); FMA2(acc[3][2], c3.y, h2.y);
        FMA2(acc[3][3], c3.x, h3.x); FMA2(acc[3][3], c3.y, h3.y);
        c0 = n0; c1 = n1; c2 = n2; c3 = n3;
    }

    // stage C: dump partials (per row: float4 over 4 b)
    #pragma unroll
    for (int j = 0; j < 4; j++) {
        float4 v = make_float4(
            f2lo(acc[j][0]) + f2hi(acc[j][0]),
            f2lo(acc[j][1]) + f2hi(acc[j][1]),
            f2lo(acc[j][2]) + f2hi(acc[j][2]),
            f2lo(acc[j][3]) + f2hi(acc[j][3]));
        *(float4*)&red[((r0 + j) * 8 + ksub) * 16 + bs * 4] = v;
    }
    __syncthreads();

    // stage D: reduce + nonlinearity + state update
    if (tid < 128) {
        int ko_l = tid & 7, b = tid >> 3;
        int ko = bkid * 8 + ko_l;
        float gsum[4];
        #pragma unroll
        for (int g = 0; g < 4; g++) {
            int r = g * 8 + ko_l;
            float ss = 0.f;
            #pragma unroll
            for (int ks = 0; ks < 8; ks++) ss += red[(r * 8 + ks) * 16 + b];
            gsum[g] = ss;
        }
        float pi, pf, pg, po;
        if (LAYER) {
            pi = bias1[ko]; pf = bias1[512 + ko];
            pg = bias1[1024 + ko]; po = bias1[1536 + ko];
        } else {
            const float* xg = xg0d + ((size_t)(n * Tc + tok) * Bc + b) * H4 + ko;
            pi = xg[0]; pf = xg[512]; pg = xg[1024]; po = xg[1536];
        }
        float gi = gsum[0] + pi, gf = gsum[1] + pf, gg = gsum[2] + pg, go = gsum[3] + po;
        float si = 1.f / (1.f + expf(-gi));
        float sf = 1.f / (1.f + expf(-gf));
        float so = 1.f / (1.f + expf(-go));
        int idx = b * Hc + ko;
        float cn = sf * cst[idx] + si * tanhf(gg);
        float hn = so * tanhf(cn);
        cst[idx]  = cn;
        hout[idx] = hn;
        if (LAYER) {
            g_out1[((size_t)(n * Tc + tok) * Bc + b) * H2 + dir * Hc + ko] = hn;
        } else {
            g_x1[((size_t)tok * Bc + b) * H2 + dir * Hc + ko] = hn;
        }
    }
    grid_bar(sense);
}

#define HS_BYTES (16 * SHS * 4)            // 99072
#define LSTM_SMEM (HS_BYTES + 32 * 8 * 16 * 4)

__global__ __launch_bounds__(256, 1) void lstm_persist(
    const float* __restrict__ b1f_, const float* __restrict__ b1b_)
{
    extern __shared__ __align__(16) char smemc[];
    float* hs  = (float*)smemc;
    float* red = (float*)(smemc + HS_BYTES);

    int tid = threadIdx.x, bid = blockIdx.x;
    int dir = bid >> 6, bkid = bid & 63;
    int ksub = tid & 7, bs = (tid >> 3) & 3, rg = tid >> 5;

    const float* bias1 = dir ? b1b_ : b1f_;
    const float* xg0d  = g_xg0 + (size_t)dir * NTB * H4;

    unsigned sense = 0;
    int p0 = 0, p1 = 0;

    for (int t = 0; t < Tc; t++) {
        for (int n = 0; n < Nc; n++) {
            int L = t + 1;
            for (int s = 0; s < L; s++) {
                int tok = dir ? (L - 1 - s) : s;
                lstm_do_step<0>(tid, dir, bkid, ksub, bs, rg, hs, red,
                                n, tok, p0, bias1, xg0d, sense);
                p0 ^= 1;
            }
            for (int s = 0; s < L; s++) {
                int tok = dir ? (L - 1 - s) : s;
                lstm_do_step<1>(tid, dir, bkid, ksub, bs, rg, hs, red,
                                n, tok, p1, bias1, xg0d, sense);
                p1 ^= 1;
            }
        }
    }
}

// ================= bf16-split mma.sync FC =================
#define FCBM 128
#define FCBN 128
#define FCBK 64
#define PADK 72
#define FC_SMEM (4 * FCBM * PADK * 2)

__device__ __forceinline__ void mma16816(
    float& c0, float& c1, float& c2, float& c3,
    uint32_t a0, uint32_t a1, uint32_t a2, uint32_t a3,
    uint32_t b0, uint32_t b1)
{
    asm volatile(
        "mma.sync.aligned.m16n8k16.row.col.f32.bf16.bf16.f32 "
        "{%0,%1,%2,%3}, {%4,%5,%6,%7}, {%8,%9}, {%0,%1,%2,%3};"
        : "+f"(c0), "+f"(c1), "+f"(c2), "+f"(c3)
        : "r"(a0), "r"(a1), "r"(a2), "r"(a3), "r"(b0), "r"(b1));
}

__global__ __launch_bounds__(256) void fc_wmma(
    const float* __restrict__ bias, float* __restrict__ out)
{
    extern __shared__ __align__(16) __nv_bfloat16 sm[];
    __nv_bfloat16* sAh = sm;
    __nv_bfloat16* sAl = sm + FCBM * PADK;
    __nv_bfloat16* sBh = sm + 2 * FCBM * PADK;
    __nv_bfloat16* sBl = sm + 3 * FCBM * PADK;

    int tid = threadIdx.x;
    int wid = tid >> 5, lane = tid & 31;
    int g = lane >> 2, q = lane & 3;
    int wm = wid & 3, wn = wid >> 2;
    int bm = blockIdx.y * FCBM, bn = blockIdx.x * FCBN;

    const uint4* A4h = (const uint4*)g_Ahi;
    const uint4* A4l = (const uint4*)g_Alo;
    const uint4* B4h = (const uint4*)g_Bhi;
    const uint4* B4l = (const uint4*)g_Blo;
    const uint4 z4 = make_uint4(0, 0, 0, 0);

    float acc[2][8][4];
    #pragma unroll
    for (int i = 0; i < 2; i++)
        #pragma unroll
        for (int j = 0; j < 8; j++)
            #pragma unroll
            for (int e = 0; e < 4; e++) acc[i][j][e] = 0.f;

    const uint32_t* sA32h = (const uint32_t*)sAh;
    const uint32_t* sA32l = (const uint32_t*)sAl;
    const uint32_t* sB32h = (const uint32_t*)sBh;
    const uint32_t* sB32l = (const uint32_t*)sBl;

    for (int kc = 0; kc < H2 / FCBK; kc++) {
        __syncthreads();
        #pragma unroll
        for (int it = 0; it < 4; it++) {
            int idx = tid + it * 256;
            int m = idx >> 3, kg = idx & 7;
            int gm = bm + m;
            size_t gi = (size_t)gm * (H2 / 8) + kc * 8 + kg;
            uint4 vh = z4, vl = z4;
            if (gm < NTB) { vh = A4h[gi]; vl = A4l[gi]; }
            *(uint4*)&sAh[m * PADK + kg * 8] = vh;
            *(uint4*)&sAl[m * PADK + kg * 8] = vl;
        }
        #pragma unroll
        for (int it = 0; it < 4; it++) {
            int idx = tid + it * 256;
            int n = idx >> 3, kg = idx & 7;
            int gn = bn + n;
            uint4 vh = z4, vl = z4;
            if (gn < Vc) {
                size_t gi = (size_t)gn * (H2 / 8) + kc * 8 + kg;
                vh = B4h[gi]; vl = B4l[gi];
            }
            *(uint4*)&sBh[n * PADK + kg * 8] = vh;
            *(uint4*)&sBl[n * PADK + kg * 8] = vl;
        }
        __syncthreads();

        #pragma unroll
        for (int ks = 0; ks < 4; ks++) {
            uint32_t ah[2][4], al[2][4];
            #pragma unroll
            for (int mi = 0; mi < 2; mi++) {
                int r0 = (wm * 32 + mi * 16 + g) * (PADK / 2);
                int r8 = r0 + 8 * (PADK / 2);
                int w0 = ks * 8 + q, w4 = w0 + 4;
                ah[mi][0] = sA32h[r0 + w0]; ah[mi][1] = sA32h[r8 + w0];
                ah[mi][2] = sA32h[r0 + w4]; ah[mi][3] = sA32h[r8 + w4];
                al[mi][0] = sA32l[r0 + w0]; al[mi][1] = sA32l[r8 + w0];
                al[mi][2] = sA32l[r0 + w4]; al[mi][3] = sA32l[r8 + w4];
            }
            #pragma unroll
            for (int ni = 0; ni < 8; ni++) {
                int nr = (wn * 64 + ni * 8 + g) * (PADK / 2);
                int w0 = ks * 8 + q, w4 = w0 + 4;
                uint32_t bh0 = sB32h[nr + w0], bh1 = sB32h[nr + w4];
                uint32_t bl0 = sB32l[nr + w0], bl1 = sB32l[nr + w4];
                #pragma unroll
                for (int mi = 0; mi < 2; mi++) {
                    float* c = acc[mi][ni];
                    mma16816(c[0], c[1], c[2], c[3],
                             ah[mi][0], ah[mi][1], ah[mi][2], ah[mi][3], bh0, bh1);
                    mma16816(c[0], c[1], c[2], c[3],
                             al[mi][0], al[mi][1], al[mi][2], al[mi][3], bh0, bh1);
                    mma16816(c[0], c[1], c[2], c[3],
                             ah[mi][0], ah[mi][1], ah[mi][2], ah[mi][3], bl0, bl1);
                }
            }
        }
    }

    #pragma unroll
    for (int mi = 0; mi < 2; mi++) {
        int row0 = bm + wm * 32 + mi * 16 + g;
        int row1 = row0 + 8;
        #pragma unroll
        for (int ni = 0; ni < 8; ni++) {
            int col = bn + wn * 64 + ni * 8 + q * 2;
            if (col >= Vc) continue;
            float b0 = bias[col], b1 = bias[col + 1];
            const float* c = acc[mi][ni];
            if (row0 < NTB) {
                float2 v = make_float2(c[0] + b0, c[1] + b1);
                *(float2*)&out[(size_t)row0 * Vc + col] = v;
            }
            if (row1 < NTB) {
                float2 v = make_float2(c[2] + b0, c[3] + b1);
                *(float2*)&out[(size_t)row1 * Vc + col] = v;
            }
        }
    }
}

// ---------------- convA ----------------
__global__ void convA_k(const float* __restrict__ in)
{
    int i = blockIdx.x * 256 + threadIdx.x;
    if (i < NTB * H2) {
        float v = in[i];
        __nv_bfloat16 h = __float2bfloat16(v);
        g_Ahi[i] = h;
        g_Alo[i] = __float2bfloat16(v - __bfloat162float(h));
    }
}

// ---------------- host ----------------
extern "C" void kernel_launch(void* const* d_in, const int* in_sizes, int n_in,
                              void* d_out, int out_size)
{
    const float* img   = (const float*)d_in[0];
    const int*   caps  = (const int*)  d_in[1];
    const float* Wh1   = (const float*)d_in[2];
    const float* bh1   = (const float*)d_in[3];
    const float* Wh2   = (const float*)d_in[4];
    const float* bh2   = (const float*)d_in[5];
    const float* Wc1   = (const float*)d_in[6];
    const float* bc1   = (const float*)d_in[7];
    const float* Wc2   = (const float*)d_in[8];
    const float* bc2   = (const float*)d_in[9];
    const float* emb   = (const float*)d_in[10];
    const float* Wih0f = (const float*)d_in[11];
    const float* Whh0f = (const float*)d_in[12];
    const float* b0f   = (const float*)d_in[13];
    const float* Wih0b = (const float*)d_in[14];
    const float* Whh0b = (const float*)d_in[15];
    const float* b0b   = (const float*)d_in[16];
    const float* Wih1f = (const float*)d_in[17];
    const float* Whh1f = (const float*)d_in[18];
    const float* b1f   = (const float*)d_in[19];
    const float* Wih1b = (const float*)d_in[20];
    const float* Whh1b = (const float*)d_in[21];
    const float* b1b   = (const float*)d_in[22];
    const float* Wfc   = (const float*)d_in[23];
    const float* bfc   = (const float*)d_in[24];
    float* outp = (float*)d_out;

    float *p_out1, *p_W0T, *p_W1T;
    cudaGetSymbolAddress((void**)&p_out1, g_out1);
    cudaGetSymbolAddress((void**)&p_W0T,  g_W0T);
    cudaGetSymbolAddress((void**)&p_W1T,  g_W1T);

    const size_t W1ROW = (size_t)H4 * (Hc + H2);

    // Launch 0: transposes + MLP stage1 + gather + convB (fused 1-D dispatch)
    TParams6 tp;
    tp.p[0] = { Whh0f, p_W0T,                 Hc, Hc };
    tp.p[1] = { Whh0b, p_W0T + (size_t)H4*Hc, Hc, Hc };
    tp.p[2] = { Whh1f, p_W1T,                 Hc, Hc + H2 };
    tp.p[3] = { Wih1f, p_W1T + Hc,            H2, Hc + H2 };
    tp.p[4] = { Whh1b, p_W1T + W1ROW,         Hc, Hc + H2 };
    tp.p[5] = { Wih1b, p_W1T + W1ROW + Hc,    H2, Hc + H2 };
    pre1<<<P1_TOTAL, 256>>>(tp, img, Wh1, bh1, Wc1, bc1, caps, emb, Wfc);

    // Launch 1: MLP stage2 (dual)
    pre2k<<<dim3(Hc/64, 1, 2), 256>>>(Wh2, bh2, Wc2, bc2);

    // Launch 2: xg0 GEMMs (z=0,1) + state broadcast (z=2)
    pre3<<<dim3(H4/128, (NTB+127)/128, 3), 256>>>(Wih0f, b0f, Wih0b, b0b);

    // Launch 3: persistent recurrent chain
    cudaFuncSetAttribute(lstm_persist, cudaFuncAttributeMaxDynamicSharedMemorySize, LSTM_SMEM);
    lstm_persist<<<NBLK, 256, LSTM_SMEM>>>(b1f, b1b);

    // Launch 4: out1 -> bf16 hi/lo
    convA_k<<<(NTB*H2 + 255)/256, 256>>>(p_out1);

    // Launch 5: tensor-core FC
    cudaFuncSetAttribute(fc_wmma, cudaFuncAttributeMaxDynamicSharedMemorySize, FC_SMEM);
    fc_wmma<<<dim3((Vc + FCBN - 1)/FCBN, (NTB + FCBM - 1)/FCBM), 256, FC_SMEM>>>(bfc, outp);
}

// round 11
// speedup vs baseline: 1.7071x; 1.7071x over previous
#include <cuda_runtime.h>
#include <cuda_bf16.h>
#include <math.h>
#include <stdint.h>

// Problem constants
#define Bc 16
#define Nc 5
#define Tc 10
#define Hc 512
#define Ec 250
#define Vc 30000
#define Fc 2048
#define H4 2048
#define H2 1024
#define NTB (Nc*Tc*Bc)   // 800
#define NBLK 128

// packed fp32x2 FMA (SASS FFMA2)
#define FMA2(d, a, b) asm("fma.rn.f32x2 %0, %1, %2, %0;" : "+l"(d) : "l"(a), "l"(b))

__device__ __forceinline__ float f2lo(unsigned long long v) { return __uint_as_float((unsigned)v); }
__device__ __forceinline__ float f2hi(unsigned long long v) { return __uint_as_float((unsigned)(v >> 32)); }
__device__ __forceinline__ unsigned long long splat2(float w) {
    unsigned long long d;
    asm("mov.b64 %0, {%1, %1};" : "=l"(d) : "r"(__float_as_uint(w)));
    return d;
}

// hs bank-swizzled slot address: (k, q) -> byte offset; q = b-group (4 floats)
__device__ __forceinline__ int hs_off(int k, int q) {
    return (((k) << 6) | ((q) << 4)) ^ ((k & 0x1C) << 2);
}

// ---------------- device scratch ----------------
__device__ __align__(16) float g_tmp[Bc*H2];
__device__ __align__(16) float g_tmp2[Bc*H2];
__device__ __align__(16) float g_h0[Bc*Hc];          // [b][k]
__device__ __align__(16) float g_c0[Bc*Hc];          // [b][k]
__device__ __align__(16) float g_hst[4][2][Hc*Bc];   // state h, k-major [k][b]
__device__ __align__(16) float g_cst[4][Hc*Bc];      // state c, k-major
__device__ __align__(16) float g_x0[NTB*Ec];
__device__ __align__(16) float g_xg0[2*NTB*H4];
__device__ __align__(16) float g_x1[Tc*H2*Bc];       // [t][k][b] k-major
__device__ __align__(16) float g_out1[NTB*H2];
__device__ __align__(16) float g_W0T[2*H4*Hc];
__device__ __align__(16) float g_W1T[2*H4*(Hc+H2)];
__device__ __align__(16) __nv_bfloat16 g_Ahi[NTB*H2];
__device__ __align__(16) __nv_bfloat16 g_Alo[NTB*H2];
__device__ __align__(16) __nv_bfloat16 g_Bhi[(size_t)Vc*H2];
__device__ __align__(16) __nv_bfloat16 g_Blo[(size_t)Vc*H2];

__device__ unsigned g_barcnt = 0;
__device__ unsigned g_barsense = 0;

// ---------------- shared sgemm body (64x64 tiles) ----------------
struct TParam { const float* in; float* out; int R; int ostride; };
struct TParams6 { TParam p[6]; };

__device__ __forceinline__ void sgemm_body(
    const float* A, const float* W, const float* bias, float* C,
    int M, int N, int K, int relu, int bm, int bn, int tid,
    float* As, float* Bs)
{
    int tm = (tid >> 4) << 2;
    int tn = (tid & 15) << 2;
    float acc[4][4] = {};
    for (int k0 = 0; k0 < K; k0 += 16) {
        #pragma unroll
        for (int e = 0; e < 4; e++) {
            int idx = tid + e * 256;
            int r = idx >> 4, c = idx & 15;
            int gr = bm + r, gc = k0 + c;
            As[c * 64 + r] = (gr < M && gc < K) ? A[(size_t)gr * K + gc] : 0.f;
        }
        #pragma unroll
        for (int e = 0; e < 4; e++) {
            int idx = tid + e * 256;
            int r = idx >> 6, c = idx & 63;
            int gr = k0 + r, gc = bn + c;
            Bs[r * 64 + c] = (gr < K && gc < N) ? W[(size_t)gr * N + gc] : 0.f;
        }
        __syncthreads();
        #pragma unroll
        for (int kk = 0; kk < 16; kk++) {
            float4 a4 = *(const float4*)&As[kk * 64 + tm];
            float4 b4 = *(const float4*)&Bs[kk * 64 + tn];
            float a[4] = {a4.x, a4.y, a4.z, a4.w};
            float b[4] = {b4.x, b4.y, b4.z, b4.w};
            #pragma unroll
            for (int i = 0; i < 4; i++)
                #pragma unroll
                for (int j = 0; j < 4; j++)
                    acc[i][j] = fmaf(a[i], b[j], acc[i][j]);
        }
        __syncthreads();
    }
    #pragma unroll
    for (int i = 0; i < 4; i++) {
        int gm = bm + tm + i;
        if (gm >= M) continue;
        #pragma unroll
        for (int j = 0; j < 4; j++) {
            int gn = bn + tn + j;
            if (gn >= N) continue;
            float v = acc[i][j] + bias[gn];
            if (relu) v = fmaxf(v, 0.f);
            C[(size_t)gm * N + gn] = v;
        }
    }
}

// ================= pre1: transposes + MLP stage1 + gather + convB =================
#define P1_TRANS 12288           // 6 * 64 * 32
#define P1_MLP   (P1_TRANS + 32)
#define P1_GATH  (P1_MLP + 800)
#define P1_TOTAL (P1_GATH + 30016)   // 938*32 convB blocks

__global__ __launch_bounds__(256) void pre1(
    TParams6 tp,
    const float* __restrict__ img,
    const float* __restrict__ Wh1, const float* __restrict__ bh1,
    const float* __restrict__ Wc1, const float* __restrict__ bc1,
    const int* __restrict__ caps, const float* __restrict__ emb,
    const float* __restrict__ Wfc)
{
    __shared__ float sh[2048];
    int id = blockIdx.x, tid = threadIdx.x;
    int tx = tid & 31, ty = tid >> 5;

    if (id < P1_TRANS) {
        int which = id / 2048, rem = id % 2048;
        int bx = rem & 63, by = rem >> 6;
        TParam p = tp.p[which];
        int c0 = bx * 32, r0 = by * 32;
        if (r0 >= p.R) return;
        for (int j = ty; j < 32; j += 8) {
            int r = r0 + j, c = c0 + tx;
            sh[j * 33 + tx] = (r < p.R) ? p.in[(size_t)r * H4 + c] : 0.f;
        }
        __syncthreads();
        for (int j = ty; j < 32; j += 8) {
            int c = c0 + j, r = r0 + tx;
            if (r < p.R) p.out[(size_t)c * p.ostride + r] = sh[tx * 33 + j];
        }
    } else if (id < P1_MLP) {
        int sub = id - P1_TRANS;
        int z = sub >> 4, bx = sub & 15;
        sgemm_body(img, z ? Wc1 : Wh1, z ? bc1 : bh1, z ? g_tmp2 : g_tmp,
                   Bc, H2, Fc, 1, 0, bx * 64, tid, sh, sh + 1024);
    } else if (id < P1_GATH) {
        int rid = id - P1_MLP;
        int b = rid & 15;
        int nt = rid >> 4;
        int n = nt / Tc, t = nt % Tc;
        int tok = caps[b * (Nc * Tc) + n * Tc + t];
        const float* e = emb + (size_t)tok * Ec;
        float* o = g_x0 + (size_t)rid * Ec;
        for (int i = tid; i < Ec; i += 256) o[i] = e[i];
    } else {
        int sub = id - P1_GATH;
        int n0 = (sub % 938) * 32, k0 = (sub / 938) * 32;
        for (int j = ty; j < 32; j += 8) {
            int k = k0 + j, n = n0 + tx;
            sh[j * 33 + tx] = (n < Vc) ? Wfc[(size_t)k * Vc + n] : 0.f;
        }
        __syncthreads();
        for (int j = ty; j < 32; j += 8) {
            int n = n0 + j, k = k0 + tx;
            if (n < Vc) {
                float v = sh[tx * 33 + j];
                __nv_bfloat16 h = __float2bfloat16(v);
                g_Bhi[(size_t)n * H2 + k] = h;
                g_Blo[(size_t)n * H2 + k] = __float2bfloat16(v - __bfloat162float(h));
            }
        }
    }
}

// ================= pre2: MLP stage2 (dual via z) =================
__global__ __launch_bounds__(256) void pre2k(
    const float* __restrict__ Wh2, const float* __restrict__ bh2,
    const float* __restrict__ Wc2, const float* __restrict__ bc2)
{
    __shared__ float sh[2048];
    int z = blockIdx.z;
    sgemm_body(z ? g_tmp2 : g_tmp, z ? Wc2 : Wh2, z ? bc2 : bh2, z ? g_c0 : g_h0,
               Bc, Hc, H2, 1, 0, blockIdx.x * 64, threadIdx.x, sh, sh + 1024);
}

// ================= pre3: xg0 GEMM (z=0,1) + state broadcast k-major (z=2) =================
__global__ __launch_bounds__(256) void pre3(
    const float* __restrict__ B0, const float* __restrict__ bias0,
    const float* __restrict__ B1, const float* __restrict__ bias1)
{
    __shared__ __align__(16) float As[2][16][128];
    __shared__ __align__(16) float Bs[2][16][256];

    if (blockIdx.z == 2) {
        int lin = blockIdx.y * 16 + blockIdx.x;
        if (lin < 32) {
            int i = lin * 256 + threadIdx.x;   // i = k*16 + b
            int k = i >> 4, b = i & 15;
            float h = g_h0[b * Hc + k];
            float c = g_c0[b * Hc + k];
            #pragma unroll
            for (int s = 0; s < 4; s++) {
                g_hst[s][0][i] = h;
                g_cst[s][i]    = c;
            }
        }
        return;
    }

    const float* A = g_x0;
    const float* B = blockIdx.z ? B1 : B0;
    const float* bias = blockIdx.z ? bias1 : bias0;
    float* C = blockIdx.z ? (g_xg0 + (size_t)NTB * H4) : g_xg0;
    const int M = NTB, N = H4, K = Ec;

    int tid = threadIdx.x;
    int bm = blockIdx.y * 128, bn = blockIdx.x * 128;
    int tx = tid & 15, ty = tid >> 4;
    int ar = tid >> 2, ac = (tid & 3) * 4;
    int br = tid >> 5, bc = (tid & 31) * 4;

    unsigned long long acc[4][8];
    #pragma unroll
    for (int i = 0; i < 4; i++)
        #pragma unroll
        for (int j = 0; j < 8; j++) acc[i][j] = 0ull;

    float a0[4], a1[4], b0[4], b1[4];
    int KT = (K + 15) / 16;

#define LOADTILE(KT_) do {                                                        \
    int k0 = (KT_) * 16;                                                          \
    int gr0 = bm + ar, gr1 = bm + ar + 64;                                        \
    _Pragma("unroll") for (int j = 0; j < 4; j++) {                               \
        int gk = k0 + ac + j;                                                     \
        bool ok = (gk < K);                                                       \
        a0[j] = (ok && gr0 < M) ? A[(size_t)gr0 * K + gk] : 0.f;                  \
        a1[j] = (ok && gr1 < M) ? A[(size_t)gr1 * K + gk] : 0.f;                  \
    }                                                                             \
    int gk0 = k0 + br, gk1 = k0 + br + 8;                                         \
    _Pragma("unroll") for (int j = 0; j < 4; j++) {                               \
        int gc = bn + bc + j;                                                     \
        b0[j] = (gk0 < K) ? B[(size_t)gk0 * N + gc] : 0.f;                        \
        b1[j] = (gk1 < K) ? B[(size_t)gk1 * N + gc] : 0.f;                        \
    }                                                                             \
} while (0)

#define STORETILE(BUF_) do {                                                      \
    _Pragma("unroll") for (int j = 0; j < 4; j++) {                               \
        As[BUF_][ac + j][ar]      = a0[j];                                        \
        As[BUF_][ac + j][ar + 64] = a1[j];                                        \
        Bs[BUF_][br][(bc + j) * 2]         = b0[j];                               \
        Bs[BUF_][br][(bc + j) * 2 + 1]     = b0[j];                               \
        Bs[BUF_][br + 8][(bc + j) * 2]     = b1[j];                               \
        Bs[BUF_][br + 8][(bc + j) * 2 + 1] = b1[j];                               \
    }                                                                             \
} while (0)

    LOADTILE(0);
    STORETILE(0);
    __syncthreads();

    for (int kt = 0; kt < KT; kt++) {
        int cur = kt & 1;
        if (kt + 1 < KT) LOADTILE(kt + 1);
        #pragma unroll
        for (int k = 0; k < 16; k++) {
            unsigned long long a2[4], b2[8];
            #pragma unroll
            for (int i = 0; i < 4; i++)
                a2[i] = *(const unsigned long long*)&As[cur][k][ty * 8 + 2 * i];
            #pragma unroll
            for (int j = 0; j < 8; j++)
                b2[j] = *(const unsigned long long*)&Bs[cur][k][(tx + 16 * j) * 2];
            #pragma unroll
            for (int i = 0; i < 4; i++)
                #pragma unroll
                for (int j = 0; j < 8; j++)
                    FMA2(acc[i][j], a2[i], b2[j]);
        }
        if (kt + 1 < KT) STORETILE(cur ^ 1);
        __syncthreads();
    }

    #pragma unroll
    for (int j = 0; j < 8; j++) {
        int col = bn + tx + 16 * j;
        float bb = bias[col];
        #pragma unroll
        for (int i = 0; i < 4; i++) {
            int r0 = bm + ty * 8 + 2 * i;
            float lo = f2lo(acc[i][j]) + bb;
            float hi = f2hi(acc[i][j]) + bb;
            if (r0 < M)     C[(size_t)r0 * N + col] = lo;
            if (r0 + 1 < M) C[(size_t)(r0 + 1) * N + col] = hi;
        }
    }
#undef LOADTILE
#undef STORETILE
}

// ================= persistent recurrent kernel (ROUND-8 PROVEN VERSION) =================
__device__ __forceinline__ void grid_bar(unsigned& sense)
{
    __syncthreads();
    sense ^= 1;
    if (threadIdx.x == 0) {
        __threadfence();
        unsigned old = atomicAdd(&g_barcnt, 1);
        if (old == NBLK - 1) {
            g_barcnt = 0;
            __threadfence();
            atomicExch(&g_barsense, sense);
        } else {
            while (*(volatile unsigned*)&g_barsense != sense) __nanosleep(32);
        }
        __threadfence();
    }
    __syncthreads();
}

template<int LAYER>
__device__ __forceinline__ void lstm_do_step(
    int tid, int dir, int bkid, int ksub, int bs, int rg,
    char* hsb, float* red,
    int n, int tok, int par,
    const float* bias1, const float* xg0d, unsigned& sense)
{
    const int K = LAYER ? (Hc + H2) : Hc;
    int slot = LAYER ? (2 + dir) : dir;
    const float* hglob = &g_hst[slot][par][0];
    float* hout = &g_hst[slot][par ^ 1][0];
    float* cst  = &g_cst[slot][0];
    const float* WT = LAYER ? (g_W1T + (size_t)dir * H4 * (Hc + H2))
                            : (g_W0T + (size_t)dir * H4 * Hc);

    // stage A: stage h (and x1 for layer1) into bank-swizzled smem
    {
        const float* x1g = g_x1 + (size_t)tok * H2 * Bc;
        int nf4 = K * 4;
        for (int idx = tid; idx < nf4; idx += 256) {
            int k = idx >> 2, q = idx & 3;
            float4 v;
            if (!LAYER || k < Hc) v = *(const float4*)&hglob[k * Bc + q * 4];
            else                  v = *(const float4*)&x1g[(size_t)(k - Hc) * Bc + q * 4];
            *(float4*)(hsb + hs_off(k, q)) = v;
        }
    }
    __syncthreads();

    // stage B: partial dots with register-double-buffered weight loads
    int r0 = rg * 4;
    const float4* p0;
    const float4* p1;
    const float4* p2;
    const float4* p3;
    {
        int m0 = ((r0 + 0) >> 3) * Hc + bkid * 8 + ((r0 + 0) & 7);
        int m1 = ((r0 + 1) >> 3) * Hc + bkid * 8 + ((r0 + 1) & 7);
        int m2 = ((r0 + 2) >> 3) * Hc + bkid * 8 + ((r0 + 2) & 7);
        int m3 = ((r0 + 3) >> 3) * Hc + bkid * 8 + ((r0 + 3) & 7);
        p0 = (const float4*)(WT + (size_t)m0 * K);
        p1 = (const float4*)(WT + (size_t)m1 * K);
        p2 = (const float4*)(WT + (size_t)m2 * K);
        p3 = (const float4*)(WT + (size_t)m3 * K);
    }
    unsigned long long a00 = 0, a01 = 0, a10 = 0, a11 = 0,
                       a20 = 0, a21 = 0, a30 = 0, a31 = 0;
    const int K32 = K / 32;
    float4 c0 = p0[ksub], c1 = p1[ksub], c2 = p2[ksub], c3 = p3[ksub];
    #pragma unroll 2
    for (int i = 0; i < K32; i++) {
        int nf = ((i + 1 < K32) ? (i + 1) : i) * 8 + ksub;
        float4 n0 = p0[nf], n1 = p1[nf], n2 = p2[nf], n3 = p3[nf];
        int kb = i * 32 + ksub * 4;
        const float* wp0 = (const float*)&c0;
        const float* wp1 = (const float*)&c1;
        const float* wp2 = (const float*)&c2;
        const float* wp3 = (const float*)&c3;
        #pragma unroll
        for (int kk = 0; kk < 4; kk++) {
            ulonglong2 hv = *(const ulonglong2*)(hsb + hs_off(kb + kk, bs));
            unsigned long long s0 = splat2(wp0[kk]);
            unsigned long long s1 = splat2(wp1[kk]);
            unsigned long long s2 = splat2(wp2[kk]);
            unsigned long long s3 = splat2(wp3[kk]);
            FMA2(a00, s0, hv.x); FMA2(a01, s0, hv.y);
            FMA2(a10, s1, hv.x); FMA2(a11, s1, hv.y);
            FMA2(a20, s2, hv.x); FMA2(a21, s2, hv.y);
            FMA2(a30, s3, hv.x); FMA2(a31, s3, hv.y);
        }
        c0 = n0; c1 = n1; c2 = n2; c3 = n3;
    }

    // stage C: dump partials
    {
        float4 v;
        v = make_float4(f2lo(a00), f2hi(a00), f2lo(a01), f2hi(a01));
        *(float4*)&red[((r0 + 0) * 8 + ksub) * 16 + bs * 4] = v;
        v = make_float4(f2lo(a10), f2hi(a10), f2lo(a11), f2hi(a11));
        *(float4*)&red[((r0 + 1) * 8 + ksub) * 16 + bs * 4] = v;
        v = make_float4(f2lo(a20), f2hi(a20), f2lo(a21), f2hi(a21));
        *(float4*)&red[((r0 + 2) * 8 + ksub) * 16 + bs * 4] = v;
        v = make_float4(f2lo(a30), f2hi(a30), f2lo(a31), f2hi(a31));
        *(float4*)&red[((r0 + 3) * 8 + ksub) * 16 + bs * 4] = v;
    }
    __syncthreads();

    // stage D: reduce + nonlinearity + state update
    if (tid < 128) {
        int ko_l = tid & 7, b = tid >> 3;
        int ko = bkid * 8 + ko_l;
        float gsum[4];
        #pragma unroll
        for (int g = 0; g < 4; g++) {
            int r = g * 8 + ko_l;
            float ss = 0.f;
            #pragma unroll
            for (int ks = 0; ks < 8; ks++) ss += red[(r * 8 + ks) * 16 + b];
            gsum[g] = ss;
        }
        float pi, pf, pg, po;
        if (LAYER) {
            pi = bias1[ko]; pf = bias1[512 + ko];
            pg = bias1[1024 + ko]; po = bias1[1536 + ko];
        } else {
            const float* xg = xg0d + ((size_t)(n * Tc + tok) * Bc + b) * H4 + ko;
            pi = xg[0]; pf = xg[512]; pg = xg[1024]; po = xg[1536];
        }
        float gi = gsum[0] + pi, gf = gsum[1] + pf, gg = gsum[2] + pg, go = gsum[3] + po;
        float si = 1.f / (1.f + expf(-gi));
        float sf = 1.f / (1.f + expf(-gf));
        float so = 1.f / (1.f + expf(-go));
        int idx = ko * Bc + b;
        float cn = sf * cst[idx] + si * tanhf(gg);
        float hn = so * tanhf(cn);
        cst[idx]  = cn;
        hout[idx] = hn;
        if (LAYER) {
            g_out1[((size_t)(n * Tc + tok) * Bc + b) * H2 + dir * Hc + ko] = hn;
        } else {
            g_x1[((size_t)tok * H2 + dir * Hc + ko) * Bc + b] = hn;
        }
    }
    grid_bar(sense);
}

#define HS_BYTES ((Hc + H2) * 64)          // 98304
#define RED_FLOATS (32 * 8 * 16)           // 4096
#define LSTM_SMEM (HS_BYTES + RED_FLOATS * 4)

__global__ __launch_bounds__(256, 1) void lstm_persist(
    const float* __restrict__ b1f_, const float* __restrict__ b1b_)
{
    extern __shared__ __align__(16) char smemc[];
    char* hsb  = smemc;
    float* red = (float*)(smemc + HS_BYTES);

    int tid = threadIdx.x, bid = blockIdx.x;
    int dir = bid >> 6, bkid = bid & 63;
    int ksub = tid & 7, bs = (tid >> 3) & 3, rg = tid >> 5;

    const float* bias1 = dir ? b1b_ : b1f_;
    const float* xg0d  = g_xg0 + (size_t)dir * NTB * H4;

    unsigned sense = 0;
    int p0 = 0, p1 = 0;

    for (int t = 0; t < Tc; t++) {
        for (int n = 0; n < Nc; n++) {
            int L = t + 1;
            for (int s = 0; s < L; s++) {
                int tok = dir ? (L - 1 - s) : s;
                lstm_do_step<0>(tid, dir, bkid, ksub, bs, rg, hsb, red,
                                n, tok, p0, bias1, xg0d, sense);
                p0 ^= 1;
            }
            for (int s = 0; s < L; s++) {
                int tok = dir ? (L - 1 - s) : s;
                lstm_do_step<1>(tid, dir, bkid, ksub, bs, rg, hsb, red,
                                n, tok, p1, bias1, xg0d, sense);
                p1 ^= 1;
            }
        }
    }
}

// ================= bf16-split mma.sync FC =================
#define FCBM 128
#define FCBN 128
#define FCBK 64
#define PADK 72
#define FC_SMEM (4 * FCBM * PADK * 2)

__device__ __forceinline__ void mma16816(
    float& c0, float& c1, float& c2, float& c3,
    uint32_t a0, uint32_t a1, uint32_t a2, uint32_t a3,
    uint32_t b0, uint32_t b1)
{
    asm volatile(
        "mma.sync.aligned.m16n8k16.row.col.f32.bf16.bf16.f32 "
        "{%0,%1,%2,%3}, {%4,%5,%6,%7}, {%8,%9}, {%0,%1,%2,%3};"
        : "+f"(c0), "+f"(c1), "+f"(c2), "+f"(c3)
        : "r"(a0), "r"(a1), "r"(a2), "r"(a3), "r"(b0), "r"(b1));
}

__global__ __launch_bounds__(256) void fc_wmma(
    const float* __restrict__ bias, float* __restrict__ out)
{
    extern __shared__ __align__(16) __nv_bfloat16 sm[];
    __nv_bfloat16* sAh = sm;
    __nv_bfloat16* sAl = sm + FCBM * PADK;
    __nv_bfloat16* sBh = sm + 2 * FCBM * PADK;
    __nv_bfloat16* sBl = sm + 3 * FCBM * PADK;

    int tid = threadIdx.x;
    int wid = tid >> 5, lane = tid & 31;
    int g = lane >> 2, q = lane & 3;
    int wm = wid & 3, wn = wid >> 2;
    int bm = blockIdx.y * FCBM, bn = blockIdx.x * FCBN;

    const uint4* A4h = (const uint4*)g_Ahi;
    const uint4* A4l = (const uint4*)g_Alo;
    const uint4* B4h = (const uint4*)g_Bhi;
    const uint4* B4l = (const uint4*)g_Blo;
    const uint4 z4 = make_uint4(0, 0, 0, 0);

    float acc[2][8][4];
    #pragma unroll
    for (int i = 0; i < 2; i++)
        #pragma unroll
        for (int j = 0; j < 8; j++)
            #pragma unroll
            for (int e = 0; e < 4; e++) acc[i][j][e] = 0.f;

    const uint32_t* sA32h = (const uint32_t*)sAh;
    const uint32_t* sA32l = (const uint32_t*)sAl;
    const uint32_t* sB32h = (const uint32_t*)sBh;
    const uint32_t* sB32l = (const uint32_t*)sBl;

    for (int kc = 0; kc < H2 / FCBK; kc++) {
        __syncthreads();
        #pragma unroll
        for (int it = 0; it < 4; it++) {
            int idx = tid + it * 256;
            int m = idx >> 3, kg = idx & 7;
            int gm = bm + m;
            size_t gi = (size_t)gm * (H2 / 8) + kc * 8 + kg;
            uint4 vh = z4, vl = z4;
            if (gm < NTB) { vh = A4h[gi]; vl = A4l[gi]; }
            *(uint4*)&sAh[m * PADK + kg * 8] = vh;
            *(uint4*)&sAl[m * PADK + kg * 8] = vl;
        }
        #pragma unroll
        for (int it = 0; it < 4; it++) {
            int idx = tid + it * 256;
            int n = idx >> 3, kg = idx & 7;
            int gn = bn + n;
            uint4 vh = z4, vl = z4;
            if (gn < Vc) {
                size_t gi = (size_t)gn * (H2 / 8) + kc * 8 + kg;
                vh = B4h[gi]; vl = B4l[gi];
            }
            *(uint4*)&sBh[n * PADK + kg * 8] = vh;
            *(uint4*)&sBl[n * PADK + kg * 8] = vl;
        }
        __syncthreads();

        #pragma unroll
        for (int ks = 0; ks < 4; ks++) {
            uint32_t ah[2][4], al[2][4];
            #pragma unroll
            for (int mi = 0; mi < 2; mi++) {
                int r0 = (wm * 32 + mi * 16 + g) * (PADK / 2);
                int r8 = r0 + 8 * (PADK / 2);
                int w0 = ks * 8 + q, w4 = w0 + 4;
                ah[mi][0] = sA32h[r0 + w0]; ah[mi][1] = sA32h[r8 + w0];
                ah[mi][2] = sA32h[r0 + w4]; ah[mi][3] = sA32h[r8 + w4];
                al[mi][0] = sA32l[r0 + w0]; al[mi][1] = sA32l[r8 + w0];
                al[mi][2] = sA32l[r0 + w4]; al[mi][3] = sA32l[r8 + w4];
            }
            #pragma unroll
            for (int ni = 0; ni < 8; ni++) {
                int nr = (wn * 64 + ni * 8 + g) * (PADK / 2);
                int w0 = ks * 8 + q, w4 = w0 + 4;
                uint32_t bh0 = sB32h[nr + w0], bh1 = sB32h[nr + w4];
                uint32_t bl0 = sB32l[nr + w0], bl1 = sB32l[nr + w4];
                #pragma unroll
                for (int mi = 0; mi < 2; mi++) {
                    float* c = acc[mi][ni];
                    mma16816(c[0], c[1], c[2], c[3],
                             ah[mi][0], ah[mi][1], ah[mi][2], ah[mi][3], bh0, bh1);
                    mma16816(c[0], c[1], c[2], c[3],
                             al[mi][0], al[mi][1], al[mi][2], al[mi][3], bh0, bh1);
                    mma16816(c[0], c[1], c[2], c[3],
                             ah[mi][0], ah[mi][1], ah[mi][2], ah[mi][3], bl0, bl1);
                }
            }
        }
    }

    #pragma unroll
    for (int mi = 0; mi < 2; mi++) {
        int row0 = bm + wm * 32 + mi * 16 + g;
        int row1 = row0 + 8;
        #pragma unroll
        for (int ni = 0; ni < 8; ni++) {
            int col = bn + wn * 64 + ni * 8 + q * 2;
            if (col >= Vc) continue;
            float b0 = bias[col], b1 = bias[col + 1];
            const float* c = acc[mi][ni];
            if (row0 < NTB) {
                float2 v = make_float2(c[0] + b0, c[1] + b1);
                *(float2*)&out[(size_t)row0 * Vc + col] = v;
            }
            if (row1 < NTB) {
                float2 v = make_float2(c[2] + b0, c[3] + b1);
                *(float2*)&out[(size_t)row1 * Vc + col] = v;
            }
        }
    }
}

// ---------------- convA ----------------
__global__ void convA_k(const float* __restrict__ in)
{
    int i = blockIdx.x * 256 + threadIdx.x;
    if (i < NTB * H2) {
        float v = in[i];
        __nv_bfloat16 h = __float2bfloat16(v);
        g_Ahi[i] = h;
        g_Alo[i] = __float2bfloat16(v - __bfloat162float(h));
    }
}

// ---------------- host ----------------
extern "C" void kernel_launch(void* const* d_in, const int* in_sizes, int n_in,
                              void* d_out, int out_size)
{
    const float* img   = (const float*)d_in[0];
    const int*   caps  = (const int*)  d_in[1];
    const float* Wh1   = (const float*)d_in[2];
    const float* bh1   = (const float*)d_in[3];
    const float* Wh2   = (const float*)d_in[4];
    const float* bh2   = (const float*)d_in[5];
    const float* Wc1   = (const float*)d_in[6];
    const float* bc1   = (const float*)d_in[7];
    const float* Wc2   = (const float*)d_in[8];
    const float* bc2   = (const float*)d_in[9];
    const float* emb   = (const float*)d_in[10];
    const float* Wih0f = (const float*)d_in[11];
    const float* Whh0f = (const float*)d_in[12];
    const float* b0f   = (const float*)d_in[13];
    const float* Wih0b = (const float*)d_in[14];
    const float* Whh0b = (const float*)d_in[15];
    const float* b0b   = (const float*)d_in[16];
    const float* Wih1f = (const float*)d_in[17];
    const float* Whh1f = (const float*)d_in[18];
    const float* b1f   = (const float*)d_in[19];
    const float* Wih1b = (const float*)d_in[20];
    const float* Whh1b = (const float*)d_in[21];
    const float* b1b   = (const float*)d_in[22];
    const float* Wfc   = (const float*)d_in[23];
    const float* bfc   = (const float*)d_in[24];
    float* outp = (float*)d_out;

    float *p_out1, *p_W0T, *p_W1T;
    cudaGetSymbolAddress((void**)&p_out1, g_out1);
    cudaGetSymbolAddress((void**)&p_W0T,  g_W0T);
    cudaGetSymbolAddress((void**)&p_W1T,  g_W1T);

    const size_t W1ROW = (size_t)H4 * (Hc + H2);

    // Launch 0: transposes + MLP stage1 + gather + convB (fused 1-D dispatch)
    TParams6 tp;
    tp.p[0] = { Whh0f, p_W0T,                 Hc, Hc };
    tp.p[1] = { Whh0b, p_W0T + (size_t)H4*Hc, Hc, Hc };
    tp.p[2] = { Whh1f, p_W1T,                 Hc, Hc + H2 };
    tp.p[3] = { Wih1f, p_W1T + Hc,            H2, Hc + H2 };
    tp.p[4] = { Whh1b, p_W1T + W1ROW,         Hc, Hc + H2 };
    tp.p[5] = { Wih1b, p_W1T + W1ROW + Hc,    H2, Hc + H2 };
    pre1<<<P1_TOTAL, 256>>>(tp, img, Wh1, bh1, Wc1, bc1, caps, emb, Wfc);

    // Launch 1: MLP stage2 (dual)
    pre2k<<<dim3(Hc/64, 1, 2), 256>>>(Wh2, bh2, Wc2, bc2);

    // Launch 2: xg0 GEMMs (z=0,1) + k-major state broadcast (z=2)
    pre3<<<dim3(H4/128, (NTB+127)/128, 3), 256>>>(Wih0f, b0f, Wih0b, b0b);

    // Launch 3: persistent recurrent chain (round-8 proven version)
    cudaFuncSetAttribute(lstm_persist, cudaFuncAttributeMaxDynamicSharedMemorySize, LSTM_SMEM);
    lstm_persist<<<NBLK, 256, LSTM_SMEM>>>(b1f, b1b);

    // Launch 4: out1 -> bf16 hi/lo
    convA_k<<<(NTB*H2 + 255)/256, 256>>>(p_out1);

    // Launch 5: tensor-core FC
    cudaFuncSetAttribute(fc_wmma, cudaFuncAttributeMaxDynamicSharedMemorySize, FC_SMEM);
    fc_wmma<<<dim3((Vc + FCBN - 1)/FCBN, (NTB + FCBM - 1)/FCBM), 256, FC_SMEM>>>(bfc, outp);
}

// round 12
// speedup vs baseline: 1.8590x; 1.0890x over previous
#include <cuda_runtime.h>
#include <cuda_bf16.h>
#include <math.h>
#include <stdint.h>

// Problem constants
#define Bc 16
#define Nc 5
#define Tc 10
#define Hc 512
#define Ec 250
#define Vc 30000
#define Fc 2048
#define H4 2048
#define H2 1024
#define NTB (Nc*Tc*Bc)   // 800
#define NBLK 128

// packed fp32x2 FMA (SASS FFMA2)
#define FMA2(d, a, b) asm("fma.rn.f32x2 %0, %1, %2, %0;" : "+l"(d) : "l"(a), "l"(b))

__device__ __forceinline__ float f2lo(unsigned long long v) { return __uint_as_float((unsigned)v); }
__device__ __forceinline__ float f2hi(unsigned long long v) { return __uint_as_float((unsigned)(v >> 32)); }
__device__ __forceinline__ unsigned long long splat2(float w) {
    unsigned long long d;
    asm("mov.b64 %0, {%1, %1};" : "=l"(d) : "r"(__float_as_uint(w)));
    return d;
}

// hs bank-swizzled slot address: (k, q) -> byte offset; q = b-group (4 floats)
__device__ __forceinline__ int hs_off(int k, int q) {
    return (((k) << 6) | ((q) << 4)) ^ ((k & 0x1C) << 2);
}

// ---------------- device scratch ----------------
__device__ __align__(16) float g_tmp[Bc*H2];
__device__ __align__(16) float g_tmp2[Bc*H2];
__device__ __align__(16) float g_h0[Bc*Hc];          // [b][k]
__device__ __align__(16) float g_c0[Bc*Hc];          // [b][k]
__device__ __align__(16) float g_hst[4][2][Hc*Bc];   // state h, k-major [k][b]
__device__ __align__(16) float g_cst[4][Hc*Bc];      // state c, k-major
__device__ __align__(16) float g_x0[NTB*Ec];
__device__ __align__(16) float g_xg0[2*NTB*H4];
__device__ __align__(16) float g_x1[Tc*H2*Bc];       // [t][k][b] k-major
__device__ __align__(16) float g_out1[NTB*H2];
__device__ __align__(16) float g_W0T[2*H4*Hc];
__device__ __align__(16) float g_W1T[2*H4*(Hc+H2)];
__device__ __align__(16) __nv_bfloat16 g_Ahi[NTB*H2];
__device__ __align__(16) __nv_bfloat16 g_Alo[NTB*H2];
__device__ __align__(16) __nv_bfloat16 g_Bhi[(size_t)Vc*H2];
__device__ __align__(16) __nv_bfloat16 g_Blo[(size_t)Vc*H2];

__device__ unsigned g_barcnt = 0;
__device__ unsigned g_barsense = 0;

// ---------------- shared sgemm body (64x64 tiles) ----------------
struct TParam { const float* in; float* out; int R; int ostride; };
struct TParams6 { TParam p[6]; };

__device__ __forceinline__ void sgemm_body(
    const float* A, const float* W, const float* bias, float* C,
    int M, int N, int K, int relu, int bm, int bn, int tid,
    float* As, float* Bs)
{
    int tm = (tid >> 4) << 2;
    int tn = (tid & 15) << 2;
    float acc[4][4] = {};
    for (int k0 = 0; k0 < K; k0 += 16) {
        #pragma unroll
        for (int e = 0; e < 4; e++) {
            int idx = tid + e * 256;
            int r = idx >> 4, c = idx & 15;
            int gr = bm + r, gc = k0 + c;
            As[c * 64 + r] = (gr < M && gc < K) ? A[(size_t)gr * K + gc] : 0.f;
        }
        #pragma unroll
        for (int e = 0; e < 4; e++) {
            int idx = tid + e * 256;
            int r = idx >> 6, c = idx & 63;
            int gr = k0 + r, gc = bn + c;
            Bs[r * 64 + c] = (gr < K && gc < N) ? W[(size_t)gr * N + gc] : 0.f;
        }
        __syncthreads();
        #pragma unroll
        for (int kk = 0; kk < 16; kk++) {
            float4 a4 = *(const float4*)&As[kk * 64 + tm];
            float4 b4 = *(const float4*)&Bs[kk * 64 + tn];
            float a[4] = {a4.x, a4.y, a4.z, a4.w};
            float b[4] = {b4.x, b4.y, b4.z, b4.w};
            #pragma unroll
            for (int i = 0; i < 4; i++)
                #pragma unroll
                for (int j = 0; j < 4; j++)
                    acc[i][j] = fmaf(a[i], b[j], acc[i][j]);
        }
        __syncthreads();
    }
    #pragma unroll
    for (int i = 0; i < 4; i++) {
        int gm = bm + tm + i;
        if (gm >= M) continue;
        #pragma unroll
        for (int j = 0; j < 4; j++) {
            int gn = bn + tn + j;
            if (gn >= N) continue;
            float v = acc[i][j] + bias[gn];
            if (relu) v = fmaxf(v, 0.f);
            C[(size_t)gm * N + gn] = v;
        }
    }
}

// ================= pre1: transposes + MLP stage1 + gather + convB =================
#define P1_TRANS 12288           // 6 * 64 * 32
#define P1_MLP   (P1_TRANS + 32)
#define P1_GATH  (P1_MLP + 800)
#define P1_TOTAL (P1_GATH + 30016)   // 938*32 convB blocks

__global__ __launch_bounds__(256) void pre1(
    TParams6 tp,
    const float* __restrict__ img,
    const float* __restrict__ Wh1, const float* __restrict__ bh1,
    const float* __restrict__ Wc1, const float* __restrict__ bc1,
    const int* __restrict__ caps, const float* __restrict__ emb,
    const float* __restrict__ Wfc)
{
    __shared__ float sh[2048];
    int id = blockIdx.x, tid = threadIdx.x;
    int tx = tid & 31, ty = tid >> 5;

    if (id < P1_TRANS) {
        int which = id / 2048, rem = id % 2048;
        int bx = rem & 63, by = rem >> 6;
        TParam p = tp.p[which];
        int c0 = bx * 32, r0 = by * 32;
        if (r0 >= p.R) return;
        for (int j = ty; j < 32; j += 8) {
            int r = r0 + j, c = c0 + tx;
            sh[j * 33 + tx] = (r < p.R) ? p.in[(size_t)r * H4 + c] : 0.f;
        }
        __syncthreads();
        for (int j = ty; j < 32; j += 8) {
            int c = c0 + j, r = r0 + tx;
            if (r < p.R) p.out[(size_t)c * p.ostride + r] = sh[tx * 33 + j];
        }
    } else if (id < P1_MLP) {
        int sub = id - P1_TRANS;
        int z = sub >> 4, bx = sub & 15;
        sgemm_body(img, z ? Wc1 : Wh1, z ? bc1 : bh1, z ? g_tmp2 : g_tmp,
                   Bc, H2, Fc, 1, 0, bx * 64, tid, sh, sh + 1024);
    } else if (id < P1_GATH) {
        int rid = id - P1_MLP;
        int b = rid & 15;
        int nt = rid >> 4;
        int n = nt / Tc, t = nt % Tc;
        int tok = caps[b * (Nc * Tc) + n * Tc + t];
        const float* e = emb + (size_t)tok * Ec;
        float* o = g_x0 + (size_t)rid * Ec;
        for (int i = tid; i < Ec; i += 256) o[i] = e[i];
    } else {
        int sub = id - P1_GATH;
        int n0 = (sub % 938) * 32, k0 = (sub / 938) * 32;
        for (int j = ty; j < 32; j += 8) {
            int k = k0 + j, n = n0 + tx;
            sh[j * 33 + tx] = (n < Vc) ? Wfc[(size_t)k * Vc + n] : 0.f;
        }
        __syncthreads();
        for (int j = ty; j < 32; j += 8) {
            int n = n0 + j, k = k0 + tx;
            if (n < Vc) {
                float v = sh[tx * 33 + j];
                __nv_bfloat16 h = __float2bfloat16(v);
                g_Bhi[(size_t)n * H2 + k] = h;
                g_Blo[(size_t)n * H2 + k] = __float2bfloat16(v - __bfloat162float(h));
            }
        }
    }
}

// ================= pre2: MLP stage2 (dual via z) =================
__global__ __launch_bounds__(256) void pre2k(
    const float* __restrict__ Wh2, const float* __restrict__ bh2,
    const float* __restrict__ Wc2, const float* __restrict__ bc2)
{
    __shared__ float sh[2048];
    int z = blockIdx.z;
    sgemm_body(z ? g_tmp2 : g_tmp, z ? Wc2 : Wh2, z ? bc2 : bh2, z ? g_c0 : g_h0,
               Bc, Hc, H2, 1, 0, blockIdx.x * 64, threadIdx.x, sh, sh + 1024);
}

// ================= pre3: xg0 GEMM (z=0,1) + state broadcast k-major (z=2) =================
__global__ __launch_bounds__(256) void pre3(
    const float* __restrict__ B0, const float* __restrict__ bias0,
    const float* __restrict__ B1, const float* __restrict__ bias1)
{
    __shared__ __align__(16) float As[2][16][128];
    __shared__ __align__(16) float Bs[2][16][256];

    if (blockIdx.z == 2) {
        int lin = blockIdx.y * 16 + blockIdx.x;
        if (lin < 32) {
            int i = lin * 256 + threadIdx.x;   // i = k*16 + b
            int k = i >> 4, b = i & 15;
            float h = g_h0[b * Hc + k];
            float c = g_c0[b * Hc + k];
            #pragma unroll
            for (int s = 0; s < 4; s++) {
                g_hst[s][0][i] = h;
                g_cst[s][i]    = c;
            }
        }
        return;
    }

    const float* A = g_x0;
    const float* B = blockIdx.z ? B1 : B0;
    const float* bias = blockIdx.z ? bias1 : bias0;
    float* C = blockIdx.z ? (g_xg0 + (size_t)NTB * H4) : g_xg0;
    const int M = NTB, N = H4, K = Ec;

    int tid = threadIdx.x;
    int bm = blockIdx.y * 128, bn = blockIdx.x * 128;
    int tx = tid & 15, ty = tid >> 4;
    int ar = tid >> 2, ac = (tid & 3) * 4;
    int br = tid >> 5, bc = (tid & 31) * 4;

    unsigned long long acc[4][8];
    #pragma unroll
    for (int i = 0; i < 4; i++)
        #pragma unroll
        for (int j = 0; j < 8; j++) acc[i][j] = 0ull;

    float a0[4], a1[4], b0[4], b1[4];
    int KT = (K + 15) / 16;

#define LOADTILE(KT_) do {                                                        \
    int k0 = (KT_) * 16;                                                          \
    int gr0 = bm + ar, gr1 = bm + ar + 64;                                        \
    _Pragma("unroll") for (int j = 0; j < 4; j++) {                               \
        int gk = k0 + ac + j;                                                     \
        bool ok = (gk < K);                                                       \
        a0[j] = (ok && gr0 < M) ? A[(size_t)gr0 * K + gk] : 0.f;                  \
        a1[j] = (ok && gr1 < M) ? A[(size_t)gr1 * K + gk] : 0.f;                  \
    }                                                                             \
    int gk0 = k0 + br, gk1 = k0 + br + 8;                                         \
    _Pragma("unroll") for (int j = 0; j < 4; j++) {                               \
        int gc = bn + bc + j;                                                     \
        b0[j] = (gk0 < K) ? B[(size_t)gk0 * N + gc] : 0.f;                        \
        b1[j] = (gk1 < K) ? B[(size_t)gk1 * N + gc] : 0.f;                        \
    }                                                                             \
} while (0)

#define STORETILE(BUF_) do {                                                      \
    _Pragma("unroll") for (int j = 0; j < 4; j++) {                               \
        As[BUF_][ac + j][ar]      = a0[j];                                        \
        As[BUF_][ac + j][ar + 64] = a1[j];                                        \
        Bs[BUF_][br][(bc + j) * 2]         = b0[j];                               \
        Bs[BUF_][br][(bc + j) * 2 + 1]     = b0[j];                               \
        Bs[BUF_][br + 8][(bc + j) * 2]     = b1[j];                               \
        Bs[BUF_][br + 8][(bc + j) * 2 + 1] = b1[j];                               \
    }                                                                             \
} while (0)

    LOADTILE(0);
    STORETILE(0);
    __syncthreads();

    for (int kt = 0; kt < KT; kt++) {
        int cur = kt & 1;
        if (kt + 1 < KT) LOADTILE(kt + 1);
        #pragma unroll
        for (int k = 0; k < 16; k++) {
            unsigned long long a2[4], b2[8];
            #pragma unroll
            for (int i = 0; i < 4; i++)
                a2[i] = *(const unsigned long long*)&As[cur][k][ty * 8 + 2 * i];
            #pragma unroll
            for (int j = 0; j < 8; j++)
                b2[j] = *(const unsigned long long*)&Bs[cur][k][(tx + 16 * j) * 2];
            #pragma unroll
            for (int i = 0; i < 4; i++)
                #pragma unroll
                for (int j = 0; j < 8; j++)
                    FMA2(acc[i][j], a2[i], b2[j]);
        }
        if (kt + 1 < KT) STORETILE(cur ^ 1);
        __syncthreads();
    }

    #pragma unroll
    for (int j = 0; j < 8; j++) {
        int col = bn + tx + 16 * j;
        float bb = bias[col];
        #pragma unroll
        for (int i = 0; i < 4; i++) {
            int r0 = bm + ty * 8 + 2 * i;
            float lo = f2lo(acc[i][j]) + bb;
            float hi = f2hi(acc[i][j]) + bb;
            if (r0 < M)     C[(size_t)r0 * N + col] = lo;
            if (r0 + 1 < M) C[(size_t)(r0 + 1) * N + col] = hi;
        }
    }
#undef LOADTILE
#undef STORETILE
}

// ================= persistent recurrent kernel =================
__device__ __forceinline__ void grid_bar(unsigned& sense)
{
    __syncthreads();
    sense ^= 1;
    if (threadIdx.x == 0) {
        __threadfence();
        unsigned old = atomicAdd(&g_barcnt, 1);
        if (old == NBLK - 1) {
            g_barcnt = 0;
            __threadfence();
            atomicExch(&g_barsense, sense);
        } else {
            while (*(volatile unsigned*)&g_barsense != sense) __nanosleep(32);
        }
        __threadfence();
    }
    __syncthreads();
}

// red layout: row (0..31) stride 1280 B; ksub (0..15) stride 80 B; b (0..15) * 4 B
#define RED_ROWSTRIDE 1280
#define RED_BYTES (32 * RED_ROWSTRIDE)     // 40960

template<int LAYER>
__device__ __forceinline__ void lstm_do_step(
    int tid, int dir, int bkid, int ksub, int bs, int rg,
    char* hsb, char* redb,
    int n, int tok, int par,
    const float* bias1, const float* xg0d, unsigned& sense)
{
    const int K = LAYER ? (Hc + H2) : Hc;
    int slot = LAYER ? (2 + dir) : dir;
    const float* hglob = &g_hst[slot][par][0];
    float* hout = &g_hst[slot][par ^ 1][0];
    float* cst  = &g_cst[slot][0];
    const float* WT = LAYER ? (g_W1T + (size_t)dir * H4 * (Hc + H2))
                            : (g_W0T + (size_t)dir * H4 * Hc);

    // stage A: stage h (and x1 for layer1) into bank-swizzled smem
    {
        const float* x1g = g_x1 + (size_t)tok * H2 * Bc;
        int nf4 = K * 4;
        for (int idx = tid; idx < nf4; idx += 256) {
            int k = idx >> 2, q = idx & 3;
            float4 v;
            if (!LAYER || k < Hc) v = *(const float4*)&hglob[k * Bc + q * 4];
            else                  v = *(const float4*)&x1g[(size_t)(k - Hc) * Bc + q * 4];
            *(float4*)(hsb + hs_off(k, q)) = v;
        }
    }
    __syncthreads();

    // stage B: 8 rows per thread (consecutive m), 16 k-slices, double-buffered weights
    // rows: m = rg*Hc + bkid*8 + j, j = 0..7 (rg = gate)
    const float4* pw = (const float4*)(WT + (size_t)(rg * Hc + bkid * 8) * K);
    const int RS = K / 4;            // f4 row stride
    const int KI = K / 64;           // chunks (8 or 24)

    unsigned long long acc0[8], acc1[8];
    #pragma unroll
    for (int j = 0; j < 8; j++) { acc0[j] = 0ull; acc1[j] = 0ull; }

    float4 cur[8], nxt[8];
    #pragma unroll
    for (int j = 0; j < 8; j++) cur[j] = pw[j * RS + ksub];

    #pragma unroll 2
    for (int i = 0; i < KI; i++) {
        int nf = ((i + 1 < KI) ? (i + 1) : i) * 16 + ksub;
        #pragma unroll
        for (int j = 0; j < 8; j++) nxt[j] = pw[j * RS + nf];
        int kb = i * 64 + ksub * 4;
        #pragma unroll
        for (int kk = 0; kk < 4; kk++) {
            ulonglong2 hv = *(const ulonglong2*)(hsb + hs_off(kb + kk, bs));
            #pragma unroll
            for (int j = 0; j < 8; j++) {
                unsigned long long s = splat2(((const float*)&cur[j])[kk]);
                FMA2(acc0[j], s, hv.x);
                FMA2(acc1[j], s, hv.y);
            }
        }
        #pragma unroll
        for (int j = 0; j < 8; j++) cur[j] = nxt[j];
    }

    // stage C: dump partials; acc0 = (b0,b1), acc1 = (b2,b3) for each row
    #pragma unroll
    for (int j = 0; j < 8; j++) {
        int row = rg * 8 + j;
        float4 v = make_float4(f2lo(acc0[j]), f2hi(acc0[j]),
                               f2lo(acc1[j]), f2hi(acc1[j]));
        *(float4*)(redb + row * RED_ROWSTRIDE + ksub * 80 + bs * 16) = v;
    }
    __syncthreads();

    // stage D: reduce over 16 ksub + nonlinearity + state update
    if (tid < 128) {
        int ko_l = tid & 7, b = tid >> 3;
        int ko = bkid * 8 + ko_l;
        float gsum[4];
        #pragma unroll
        for (int g = 0; g < 4; g++) {
            int row = g * 8 + ko_l;
            const char* base = redb + row * RED_ROWSTRIDE;
            float ss = 0.f;
            #pragma unroll
            for (int ks = 0; ks < 16; ks++)
                ss += ((const float*)(base + ks * 80))[b];
            gsum[g] = ss;
        }
        float pi, pf, pg, po;
        if (LAYER) {
            pi = bias1[ko]; pf = bias1[512 + ko];
            pg = bias1[1024 + ko]; po = bias1[1536 + ko];
        } else {
            const float* xg = xg0d + ((size_t)(n * Tc + tok) * Bc + b) * H4 + ko;
            pi = xg[0]; pf = xg[512]; pg = xg[1024]; po = xg[1536];
        }
        float gi = gsum[0] + pi, gf = gsum[1] + pf, gg = gsum[2] + pg, go = gsum[3] + po;
        float si = 1.f / (1.f + expf(-gi));
        float sf = 1.f / (1.f + expf(-gf));
        float so = 1.f / (1.f + expf(-go));
        int idx = ko * Bc + b;
        float cn = sf * cst[idx] + si * tanhf(gg);
        float hn = so * tanhf(cn);
        cst[idx]  = cn;
        hout[idx] = hn;
        if (LAYER) {
            g_out1[((size_t)(n * Tc + tok) * Bc + b) * H2 + dir * Hc + ko] = hn;
        } else {
            g_x1[((size_t)tok * H2 + dir * Hc + ko) * Bc + b] = hn;
        }
    }
    grid_bar(sense);
}

#define HS_BYTES ((Hc + H2) * 64)          // 98304
#define LSTM_SMEM (HS_BYTES + RED_BYTES)   // 139264

__global__ __launch_bounds__(256, 1) void lstm_persist(
    const float* __restrict__ b1f_, const float* __restrict__ b1b_)
{
    extern __shared__ __align__(16) char smemc[];
    char* hsb  = smemc;
    char* redb = smemc + HS_BYTES;

    int tid = threadIdx.x, bid = blockIdx.x;
    int dir = bid >> 6, bkid = bid & 63;
    // warp-friendly mapping: all 4 bs duplicates in-warp, ksub_h = bit 5
    int ksub = (tid & 7) | (((tid >> 5) & 1) << 3);
    int bs   = (tid >> 3) & 3;
    int rg   = tid >> 6;

    const float* bias1 = dir ? b1b_ : b1f_;
    const float* xg0d  = g_xg0 + (size_t)dir * NTB * H4;

    unsigned sense = 0;
    int p0 = 0, p1 = 0;

    for (int t = 0; t < Tc; t++) {
        for (int n = 0; n < Nc; n++) {
            int L = t + 1;
            for (int s = 0; s < L; s++) {
                int tok = dir ? (L - 1 - s) : s;
                lstm_do_step<0>(tid, dir, bkid, ksub, bs, rg, hsb, redb,
                                n, tok, p0, bias1, xg0d, sense);
                p0 ^= 1;
            }
            for (int s = 0; s < L; s++) {
                int tok = dir ? (L - 1 - s) : s;
                lstm_do_step<1>(tid, dir, bkid, ksub, bs, rg, hsb, redb,
                                n, tok, p1, bias1, xg0d, sense);
                p1 ^= 1;
            }
        }
    }
}

// ================= bf16-split mma.sync FC =================
#define FCBM 128
#define FCBN 128
#define FCBK 64
#define PADK 72
#define FC_SMEM (4 * FCBM * PADK * 2)

__device__ __forceinline__ void mma16816(
    float& c0, float& c1, float& c2, float& c3,
    uint32_t a0, uint32_t a1, uint32_t a2, uint32_t a3,
    uint32_t b0, uint32_t b1)
{
    asm volatile(
        "mma.sync.aligned.m16n8k16.row.col.f32.bf16.bf16.f32 "
        "{%0,%1,%2,%3}, {%4,%5,%6,%7}, {%8,%9}, {%0,%1,%2,%3};"
        : "+f"(c0), "+f"(c1), "+f"(c2), "+f"(c3)
        : "r"(a0), "r"(a1), "r"(a2), "r"(a3), "r"(b0), "r"(b1));
}

__global__ __launch_bounds__(256) void fc_wmma(
    const float* __restrict__ bias, float* __restrict__ out)
{
    extern __shared__ __align__(16) __nv_bfloat16 sm[];
    __nv_bfloat16* sAh = sm;
    __nv_bfloat16* sAl = sm + FCBM * PADK;
    __nv_bfloat16* sBh = sm + 2 * FCBM * PADK;
    __nv_bfloat16* sBl = sm + 3 * FCBM * PADK;

    int tid = threadIdx.x;
    int wid = tid >> 5, lane = tid & 31;
    int g = lane >> 2, q = lane & 3;
    int wm = wid & 3, wn = wid >> 2;
    int bm = blockIdx.y * FCBM, bn = blockIdx.x * FCBN;

    const uint4* A4h = (const uint4*)g_Ahi;
    const uint4* A4l = (const uint4*)g_Alo;
    const uint4* B4h = (const uint4*)g_Bhi;
    const uint4* B4l = (const uint4*)g_Blo;
    const uint4 z4 = make_uint4(0, 0, 0, 0);

    float acc[2][8][4];
    #pragma unroll
    for (int i = 0; i < 2; i++)
        #pragma unroll
        for (int j = 0; j < 8; j++)
            #pragma unroll
            for (int e = 0; e < 4; e++) acc[i][j][e] = 0.f;

    const uint32_t* sA32h = (const uint32_t*)sAh;
    const uint32_t* sA32l = (const uint32_t*)sAl;
    const uint32_t* sB32h = (const uint32_t*)sBh;
    const uint32_t* sB32l = (const uint32_t*)sBl;

    for (int kc = 0; kc < H2 / FCBK; kc++) {
        __syncthreads();
        #pragma unroll
        for (int it = 0; it < 4; it++) {
            int idx = tid + it * 256;
            int m = idx >> 3, kg = idx & 7;
            int gm = bm + m;
            size_t gi = (size_t)gm * (H2 / 8) + kc * 8 + kg;
            uint4 vh = z4, vl = z4;
            if (gm < NTB) { vh = A4h[gi]; vl = A4l[gi]; }
            *(uint4*)&sAh[m * PADK + kg * 8] = vh;
            *(uint4*)&sAl[m * PADK + kg * 8] = vl;
        }
        #pragma unroll
        for (int it = 0; it < 4; it++) {
            int idx = tid + it * 256;
            int n = idx >> 3, kg = idx & 7;
            int gn = bn + n;
            uint4 vh = z4, vl = z4;
            if (gn < Vc) {
                size_t gi = (size_t)gn * (H2 / 8) + kc * 8 + kg;
                vh = B4h[gi]; vl = B4l[gi];
            }
            *(uint4*)&sBh[n * PADK + kg * 8] = vh;
            *(uint4*)&sBl[n * PADK + kg * 8] = vl;
        }
        __syncthreads();

        #pragma unroll
        for (int ks = 0; ks < 4; ks++) {
            uint32_t ah[2][4], al[2][4];
            #pragma unroll
            for (int mi = 0; mi < 2; mi++) {
                int r0 = (wm * 32 + mi * 16 + g) * (PADK / 2);
                int r8 = r0 + 8 * (PADK / 2);
                int w0 = ks * 8 + q, w4 = w0 + 4;
                ah[mi][0] = sA32h[r0 + w0]; ah[mi][1] = sA32h[r8 + w0];
                ah[mi][2] = sA32h[r0 + w4]; ah[mi][3] = sA32h[r8 + w4];
                al[mi][0] = sA32l[r0 + w0]; al[mi][1] = sA32l[r8 + w0];
                al[mi][2] = sA32l[r0 + w4]; al[mi][3] = sA32l[r8 + w4];
            }
            #pragma unroll
            for (int ni = 0; ni < 8; ni++) {
                int nr = (wn * 64 + ni * 8 + g) * (PADK / 2);
                int w0 = ks * 8 + q, w4 = w0 + 4;
                uint32_t bh0 = sB32h[nr + w0], bh1 = sB32h[nr + w4];
                uint32_t bl0 = sB32l[nr + w0], bl1 = sB32l[nr + w4];
                #pragma unroll
                for (int mi = 0; mi < 2; mi++) {
                    float* c = acc[mi][ni];
                    mma16816(c[0], c[1], c[2], c[3],
                             ah[mi][0], ah[mi][1], ah[mi][2], ah[mi][3], bh0, bh1);
                    mma16816(c[0], c[1], c[2], c[3],
                             al[mi][0], al[mi][1], al[mi][2], al[mi][3], bh0, bh1);
                    mma16816(c[0], c[1], c[2], c[3],
                             ah[mi][0], ah[mi][1], ah[mi][2], ah[mi][3], bl0, bl1);
                }
            }
        }
    }

    #pragma unroll
    for (int mi = 0; mi < 2; mi++) {
        int row0 = bm + wm * 32 + mi * 16 + g;
        int row1 = row0 + 8;
        #pragma unroll
        for (int ni = 0; ni < 8; ni++) {
            int col = bn + wn * 64 + ni * 8 + q * 2;
            if (col >= Vc) continue;
            float b0 = bias[col], b1 = bias[col + 1];
            const float* c = acc[mi][ni];
            if (row0 < NTB) {
                float2 v = make_float2(c[0] + b0, c[1] + b1);
                *(float2*)&out[(size_t)row0 * Vc + col] = v;
            }
            if (row1 < NTB) {
                float2 v = make_float2(c[2] + b0, c[3] + b1);
                *(float2*)&out[(size_t)row1 * Vc + col] = v;
            }
        }
    }
}

// ---------------- convA ----------------
__global__ void convA_k(const float* __restrict__ in)
{
    int i = blockIdx.x * 256 + threadIdx.x;
    if (i < NTB * H2) {
        float v = in[i];
        __nv_bfloat16 h = __float2bfloat16(v);
        g_Ahi[i] = h;
        g_Alo[i] = __float2bfloat16(v - __bfloat162float(h));
    }
}

// ---------------- host ----------------
extern "C" void kernel_launch(void* const* d_in, const int* in_sizes, int n_in,
                              void* d_out, int out_size)
{
    const float* img   = (const float*)d_in[0];
    const int*   caps  = (const int*)  d_in[1];
    const float* Wh1   = (const float*)d_in[2];
    const float* bh1   = (const float*)d_in[3];
    const float* Wh2   = (const float*)d_in[4];
    const float* bh2   = (const float*)d_in[5];
    const float* Wc1   = (const float*)d_in[6];
    const float* bc1   = (const float*)d_in[7];
    const float* Wc2   = (const float*)d_in[8];
    const float* bc2   = (const float*)d_in[9];
    const float* emb   = (const float*)d_in[10];
    const float* Wih0f = (const float*)d_in[11];
    const float* Whh0f = (const float*)d_in[12];
    const float* b0f   = (const float*)d_in[13];
    const float* Wih0b = (const float*)d_in[14];
    const float* Whh0b = (const float*)d_in[15];
    const float* b0b   = (const float*)d_in[16];
    const float* Wih1f = (const float*)d_in[17];
    const float* Whh1f = (const float*)d_in[18];
    const float* b1f   = (const float*)d_in[19];
    const float* Wih1b = (const float*)d_in[20];
    const float* Whh1b = (const float*)d_in[21];
    const float* b1b   = (const float*)d_in[22];
    const float* Wfc   = (const float*)d_in[23];
    const float* bfc   = (const float*)d_in[24];
    float* outp = (float*)d_out;

    float *p_out1, *p_W0T, *p_W1T;
    cudaGetSymbolAddress((void**)&p_out1, g_out1);
    cudaGetSymbolAddress((void**)&p_W0T,  g_W0T);
    cudaGetSymbolAddress((void**)&p_W1T,  g_W1T);

    const size_t W1ROW = (size_t)H4 * (Hc + H2);

    // Launch 0: transposes + MLP stage1 + gather + convB (fused 1-D dispatch)
    TParams6 tp;
    tp.p[0] = { Whh0f, p_W0T,                 Hc, Hc };
    tp.p[1] = { Whh0b, p_W0T + (size_t)H4*Hc, Hc, Hc };
    tp.p[2] = { Whh1f, p_W1T,                 Hc, Hc + H2 };
    tp.p[3] = { Wih1f, p_W1T + Hc,            H2, Hc + H2 };
    tp.p[4] = { Whh1b, p_W1T + W1ROW,         Hc, Hc + H2 };
    tp.p[5] = { Wih1b, p_W1T + W1ROW + Hc,    H2, Hc + H2 };
    pre1<<<P1_TOTAL, 256>>>(tp, img, Wh1, bh1, Wc1, bc1, caps, emb, Wfc);

    // Launch 1: MLP stage2 (dual)
    pre2k<<<dim3(Hc/64, 1, 2), 256>>>(Wh2, bh2, Wc2, bc2);

    // Launch 2: xg0 GEMMs (z=0,1) + k-major state broadcast (z=2)
    pre3<<<dim3(H4/128, (NTB+127)/128, 3), 256>>>(Wih0f, b0f, Wih0b, b0b);

    // Launch 3: persistent recurrent chain (8-rows-per-thread stage B)
    cudaFuncSetAttribute(lstm_persist, cudaFuncAttributeMaxDynamicSharedMemorySize, LSTM_SMEM);
    lstm_persist<<<NBLK, 256, LSTM_SMEM>>>(b1f, b1b);

    // Launch 4: out1 -> bf16 hi/lo
    convA_k<<<(NTB*H2 + 255)/256, 256>>>(p_out1);

    // Launch 5: tensor-core FC
    cudaFuncSetAttribute(fc_wmma, cudaFuncAttributeMaxDynamicSharedMemorySize, FC_SMEM);
    fc_wmma<<<dim3((Vc + FCBN - 1)/FCBN, (NTB + FCBM - 1)/FCBM), 256, FC_SMEM>>>(bfc, outp);
}